// round 5
// baseline (speedup 1.0000x reference)
#include <cuda_runtime.h>
#include <cstdint>

#define NPTS   300000
#define KOFF   27
#define NPAIR  100000
#define CIN    32
#define COUT   64
#define CHALF  32
#define TOT_PAIRS (KOFF * NPAIR)
#define EPS    1e-5
#define NEG_SLOPE 0.01f
#define SCAN_CHUNK 512
#define SCAN_BLOCKS ((NPTS + SCAN_CHUNK - 1) / SCAN_CHUNK)   // 586

// ---------------- device scratch (no allocations allowed) ----------------
__device__ int    g_is64;
__device__ int    g_in32[TOT_PAIRS];
__device__ int    g_out32[TOT_PAIRS];
__device__ double g_stats[16];            // [0..7]=sum, [8..15]=sumsq per group
__device__ int    g_cnt[NPTS];            // contributions per output point
__device__ int    g_start[NPTS];          // CSR row starts
__device__ int    g_cursor[NPTS];         // fill cursors
__device__ int    g_entries[TOT_PAIRS];   // CSR entries: y-row id = k*NPAIR+p
__device__ int    g_partial[1024];        // scan partials
__device__ int    g_partialExc[1024];
// 345.6 MB half-channel pair-result scratch (reused for both channel halves)
__device__ float  g_y[(size_t)TOT_PAIRS * CHALF];

// ---------------- f32x2 helpers ----------------
__device__ __forceinline__ unsigned long long fma2(unsigned long long a,
                                                   unsigned long long b,
                                                   unsigned long long c) {
    unsigned long long d;
    asm("fma.rn.f32x2 %0, %1, %2, %3;" : "=l"(d) : "l"(a), "l"(b), "l"(c));
    return d;
}
__device__ __forceinline__ unsigned long long pack2(float lo, float hi) {
    unsigned long long r;
    asm("mov.b64 %0, {%1, %2};" : "=l"(r) : "f"(lo), "f"(hi));
    return r;
}
__device__ __forceinline__ void unpack2(unsigned long long v, float& lo, float& hi) {
    asm("mov.b64 {%0, %1}, %2;" : "=f"(lo), "=f"(hi) : "l"(v));
}

// ---------------- zero counters + detect idx dtype ----------------
// Reference declares int64 indices but JAX w/o x64 silently emits int32.
// Reading int32 data as int64 fuses two indices -> almost surely >= NPTS.
__global__ void zero_kernel(const void* in_idx) {
    int gid = blockIdx.x * blockDim.x + threadIdx.x;
    int stride = gridDim.x * blockDim.x;
    for (int i = gid; i < NPTS; i += stride) g_cnt[i] = 0;
    if (gid < 16) g_stats[gid] = 0.0;
    if (blockIdx.x == 0) {
        if (threadIdx.x == 0) g_is64 = 1;
        __syncthreads();
        const long long* p = (const long long*)in_idx;
        long long slots = TOT_PAIRS / 2;
        long long s = (slots * threadIdx.x) / 256;
        long long v = p[s];
        if (v < 0 || v >= NPTS) atomicAnd(&g_is64, 0);
    }
}

// ---------------- convert indices + histogram ----------------
__global__ void convert_kernel(const void* in_idx, const void* out_idx) {
    int is64 = g_is64;
    int stride = gridDim.x * blockDim.x;
    for (int i = blockIdx.x * blockDim.x + threadIdx.x; i < TOT_PAIRS; i += stride) {
        int a, b;
        if (is64) {
            a = (int)((const long long*)in_idx)[i];
            b = (int)((const long long*)out_idx)[i];
        } else {
            a = ((const int*)in_idx)[i];
            b = ((const int*)out_idx)[i];
        }
        g_in32[i]  = a;
        g_out32[i] = b;
        atomicAdd(&g_cnt[b], 1);
    }
}

// ---------------- phase A: per-pair matmul for ONE channel half ----------------
// One warp per pair; lane owns output channel (cbase+lane). Weights for this
// k/channel packed into 16 f32x2 regs per lane. feats row read warp-broadcast
// as ulonglong2 (pre-packed x pairs). Result row (32 floats = 128B line)
// streaming-stored linearly to g_y -- NO atomics anywhere.
__global__ __launch_bounds__(128) void convA_kernel(
    const float* __restrict__ feats,
    const float* __restrict__ weight,
    int cbase)
{
    int k    = blockIdx.y;
    int lane = threadIdx.x & 31;
    int warp = threadIdx.x >> 5;

    const float* W = weight + k * (CIN * COUT);
    int c = cbase + lane;
    unsigned long long wp[16];
#pragma unroll
    for (int m = 0; m < 16; m++)
        wp[m] = pack2(W[(2 * m) * COUT + c], W[(2 * m + 1) * COUT + c]);

    const int* ii = g_in32 + k * NPAIR;
    int wstride = gridDim.x * 4;

    int p = blockIdx.x * 4 + warp;
    int pi = 0;
    if (p < NPAIR) pi = __ldg(ii + p);

    for (; p < NPAIR; p += wstride) {
        int pn = p + wstride;
        int pi_n = 0;
        if (pn < NPAIR) pi_n = __ldg(ii + pn);

        const ulonglong2* xr = (const ulonglong2*)(feats + (size_t)pi * CIN);
        unsigned long long acc = 0ull;
#pragma unroll
        for (int j = 0; j < 8; j++) {
            ulonglong2 xv = __ldg(xr + j);
            acc = fma2(xv.x, wp[2 * j],     acc);
            acc = fma2(xv.y, wp[2 * j + 1], acc);
        }
        float lo, hi;
        unpack2(acc, lo, hi);

        __stcs(g_y + (size_t)(k * NPAIR + p) * CHALF + lane, lo + hi);

        pi = pi_n;
    }
}

// ---------------- scan: per-chunk sums ----------------
__global__ __launch_bounds__(256) void scanP_kernel() {
    int b = blockIdx.x;
    int t = threadIdx.x;
    int i0 = b * SCAN_CHUNK + 2 * t;
    int s = 0;
    if (i0 < NPTS)     s += g_cnt[i0];
    if (i0 + 1 < NPTS) s += g_cnt[i0 + 1];
#pragma unroll
    for (int d = 1; d < 32; d <<= 1) s += __shfl_down_sync(0xffffffffu, s, d);
    __shared__ int ws[8];
    if ((t & 31) == 0) ws[t >> 5] = s;
    __syncthreads();
    if (t == 0) {
        int tot = 0;
#pragma unroll
        for (int w = 0; w < 8; w++) tot += ws[w];
        g_partial[b] = tot;
    }
}

// ---------------- scan: partials (single block) ----------------
__global__ __launch_bounds__(1024) void scanM_kernel() {
    __shared__ int sm[1024];
    int t = threadIdx.x;
    sm[t] = (t < SCAN_BLOCKS) ? g_partial[t] : 0;
    __syncthreads();
    for (int d = 1; d < 1024; d <<= 1) {
        int v = (t >= d) ? sm[t - d] : 0;
        __syncthreads();
        sm[t] += v;
        __syncthreads();
    }
    g_partialExc[t] = (t == 0) ? 0 : sm[t - 1];
}

// ---------------- scan: finalize starts + cursors ----------------
__global__ __launch_bounds__(256) void scanF_kernel() {
    int b = blockIdx.x;
    int t = threadIdx.x;
    int lane = t & 31;
    int wid  = t >> 5;
    int i0 = b * SCAN_CHUNK + 2 * t;
    int c0 = (i0 < NPTS)     ? g_cnt[i0]     : 0;
    int c1 = (i0 + 1 < NPTS) ? g_cnt[i0 + 1] : 0;
    int v = c0 + c1;
    int inc = v;
#pragma unroll
    for (int d = 1; d < 32; d <<= 1) {
        int n = __shfl_up_sync(0xffffffffu, inc, d);
        if (lane >= d) inc += n;
    }
    __shared__ int ws[8];
    if (lane == 31) ws[wid] = inc;
    __syncthreads();
    __shared__ int wexc[8];
    if (t == 0) {
        int acc = 0;
#pragma unroll
        for (int w = 0; w < 8; w++) { wexc[w] = acc; acc += ws[w]; }
    }
    __syncthreads();
    int texc = g_partialExc[b] + wexc[wid] + (inc - v);
    if (i0 < NPTS)     { g_start[i0] = texc;          g_cursor[i0] = texc; }
    if (i0 + 1 < NPTS) { g_start[i0 + 1] = texc + c0; g_cursor[i0 + 1] = texc + c0; }
}

// ---------------- fill CSR entries ----------------
__global__ void fill_kernel() {
    int stride = gridDim.x * blockDim.x;
    for (int e = blockIdx.x * blockDim.x + threadIdx.x; e < TOT_PAIRS; e += stride) {
        int o = g_out32[e];
        int pos = atomicAdd(&g_cursor[o], 1);
        g_entries[pos] = e;     // e == k*NPAIR+p == y-row id
    }
}

// ---------------- phase B: gather-reduce one channel half into out ----------------
__global__ __launch_bounds__(256) void gatherB_kernel(float* __restrict__ out, int cbase) {
    int lane  = threadIdx.x & 31;
    int gwarp = (blockIdx.x * blockDim.x + threadIdx.x) >> 5;
    int nwarp = (gridDim.x * blockDim.x) >> 5;

    for (int o = gwarp; o < NPTS; o += nwarp) {
        int n    = __ldg(g_cnt + o);
        int base = __ldg(g_start + o);
        float acc = 0.f;
        int e = 0;
        for (; e + 2 <= n; e += 2) {
            int r0 = __ldg(g_entries + base + e);
            int r1 = __ldg(g_entries + base + e + 1);
            float v0 = __ldcs(g_y + (size_t)r0 * CHALF + lane);
            float v1 = __ldcs(g_y + (size_t)r1 * CHALF + lane);
            acc += v0 + v1;
        }
        if (e < n) {
            int r0 = __ldg(g_entries + base + e);
            acc += __ldcs(g_y + (size_t)r0 * CHALF + lane);
        }
        out[(size_t)o * COUT + cbase + lane] = acc;   // coalesced 128B half-row
    }
}

// ---------------- group stats ----------------
__global__ __launch_bounds__(256) void reduce_kernel(const float* __restrict__ out) {
    __shared__ double ssum[16];
    int t = threadIdx.x;
    if (t < 16) ssum[t] = 0.0;
    __syncthreads();

    long long total4 = (long long)NPTS * COUT / 4;
    long long stride = (long long)gridDim.x * 256;
    float s = 0.f, q = 0.f;
    for (long long j = (long long)blockIdx.x * 256 + t; j < total4; j += stride) {
        float4 v = __ldg(((const float4*)out) + j);
        s += (v.x + v.y) + (v.z + v.w);
        q += (v.x * v.x + v.y * v.y) + (v.z * v.z + v.w * v.w);
    }
    s += __shfl_xor_sync(0xffffffffu, s, 16);
    q += __shfl_xor_sync(0xffffffffu, q, 16);
    s += __shfl_xor_sync(0xffffffffu, s, 1);
    q += __shfl_xor_sync(0xffffffffu, q, 1);
    int lane = t & 31;
    if ((lane & 16) == 0 && (lane & 1) == 0) {
        int g = lane >> 1;
        atomicAdd(&ssum[g],     (double)s);
        atomicAdd(&ssum[8 + g], (double)q);
    }
    __syncthreads();
    if (t < 16) atomicAdd(&g_stats[t], ssum[t]);
}

// ---------------- normalize + affine + LeakyReLU ----------------
__global__ __launch_bounds__(256) void norm_kernel(
    float* __restrict__ out,
    const float* __restrict__ gamma,
    const float* __restrict__ beta)
{
    int t  = threadIdx.x;
    int c4 = t & 15;
    int g  = c4 >> 1;

    double cnt = (double)NPTS * 8.0;
    double m   = g_stats[g] / cnt;
    double var = g_stats[8 + g] / cnt - m * m;
    float mean = (float)m;
    float rstd = (float)(1.0 / sqrt(var + EPS));

    float4 ga = __ldg(((const float4*)gamma) + c4);
    float4 be = __ldg(((const float4*)beta) + c4);
    float4 sc, of;
    sc.x = rstd * ga.x; of.x = be.x - mean * sc.x;
    sc.y = rstd * ga.y; of.y = be.y - mean * sc.y;
    sc.z = rstd * ga.z; of.z = be.z - mean * sc.z;
    sc.w = rstd * ga.w; of.w = be.w - mean * sc.w;

    long long total4 = (long long)NPTS * COUT / 4;
    long long stride = (long long)gridDim.x * 256;
    for (long long j = (long long)blockIdx.x * 256 + t; j < total4; j += stride) {
        float4 v = ((float4*)out)[j];
        v.x = fmaf(v.x, sc.x, of.x);
        v.y = fmaf(v.y, sc.y, of.y);
        v.z = fmaf(v.z, sc.z, of.z);
        v.w = fmaf(v.w, sc.w, of.w);
        v.x = v.x >= 0.f ? v.x : NEG_SLOPE * v.x;
        v.y = v.y >= 0.f ? v.y : NEG_SLOPE * v.y;
        v.z = v.z >= 0.f ? v.z : NEG_SLOPE * v.z;
        v.w = v.w >= 0.f ? v.w : NEG_SLOPE * v.w;
        ((float4*)out)[j] = v;
    }
}

// ---------------- launcher ----------------
extern "C" void kernel_launch(void* const* d_in, const int* in_sizes, int n_in,
                              void* d_out, int out_size) {
    const float* feats  = (const float*)d_in[0];
    const float* weight = (const float*)d_in[1];
    const float* gamma  = (const float*)d_in[2];
    const float* beta   = (const float*)d_in[3];
    const void*  in_idx = d_in[4];
    const void*  out_idx= d_in[5];
    float* out = (float*)d_out;

    zero_kernel<<<1184, 256>>>(in_idx);
    convert_kernel<<<1320, 256>>>(in_idx, out_idx);
    scanP_kernel<<<SCAN_BLOCKS, 256>>>();
    scanM_kernel<<<1, 1024>>>();
    scanF_kernel<<<SCAN_BLOCKS, 256>>>();
    fill_kernel<<<1320, 256>>>();
    convA_kernel<<<dim3(100, KOFF), 128>>>(feats, weight, 0);    // channels 0..31
    gatherB_kernel<<<2368, 256>>>(out, 0);
    convA_kernel<<<dim3(100, KOFF), 128>>>(feats, weight, CHALF); // channels 32..63
    gatherB_kernel<<<2368, 256>>>(out, CHALF);
    reduce_kernel<<<296, 256>>>(out);
    norm_kernel<<<592, 256>>>(out, gamma, beta);
}

// round 6
// speedup vs baseline: 1.1367x; 1.1367x over previous
#include <cuda_runtime.h>
#include <cstdint>

#define NPTS   300000
#define KOFF   27
#define NPAIR  100000
#define CIN    32
#define COUT   64
#define TOT_PAIRS (KOFF * NPAIR)
#define EPS    1e-5
#define NEG_SLOPE 0.01f

// ---------------- device scratch (no allocations allowed) ----------------
__device__ int    g_is64;
__device__ int    g_in32[TOT_PAIRS];
__device__ int    g_out32[TOT_PAIRS];
__device__ double g_stats[16];   // [0..7]=sum per group, [8..15]=sumsq per group

// ---------------- L1: dtype detection + stats zero ----------------
// Reference declares int64 indices but JAX w/o x64 silently emits int32.
// Reading int32 data as int64 fuses two indices -> almost surely >= NPTS.
__global__ void detect_kernel(const void* in_idx) {
    int t = threadIdx.x;
    if (t == 0) g_is64 = 1;
    if (t < 16) g_stats[t] = 0.0;
    __syncthreads();
    const long long* p = (const long long*)in_idx;
    long long slots = TOT_PAIRS / 2;
    long long s = (slots * t) / 256;
    long long v = p[s];
    if (v < 0 || v >= NPTS) atomicAnd(&g_is64, 0);
}

// ---------------- L2+L3: convert indices (split in two to position conv at slot 4) ----
__global__ void convert_kernel(const void* in_idx, const void* out_idx, int base, int count) {
    int is64 = g_is64;
    int stride = gridDim.x * blockDim.x;
    for (int i = blockIdx.x * blockDim.x + threadIdx.x; i < count; i += stride) {
        int j = base + i;
        int a, b;
        if (is64) {
            a = (int)((const long long*)in_idx)[j];
            b = (int)((const long long*)out_idx)[j];
        } else {
            a = ((const int*)in_idx)[j];
            b = ((const int*)out_idx)[j];
        }
        g_in32[j]  = a;
        g_out32[j] = b;
    }
}

// ---------------- L4 (ncu capture slot): conv gather->matmul->scatter ----------------
// One warp per pair. Lane computes channels (2*lane, 2*lane+1) of offset k;
// weights live in registers (loaded once per block). feats row = one 128B
// line, warp-broadcast 8x float4. Scatter: lane pairs shuffle-combine so 16
// even lanes issue red.global.add.v4.f32 (halves REDG lane count vs red.v2).
__global__ __launch_bounds__(128) void conv_kernel(
    const float* __restrict__ feats,
    const float* __restrict__ weight,
    float* __restrict__ out)
{
    int k    = blockIdx.y;
    int lane = threadIdx.x & 31;
    int warp = threadIdx.x >> 5;

    const float* W = weight + k * (CIN * COUT);
    float w0[CIN], w1[CIN];
#pragma unroll
    for (int i = 0; i < CIN; i++) {
        float2 wv = *(const float2*)(W + i * COUT + 2 * lane);
        w0[i] = wv.x; w1[i] = wv.y;
    }

    const int* ii = g_in32  + k * NPAIR;
    const int* oi = g_out32 + k * NPAIR;
    int wstride = gridDim.x * 4;

    for (int p = blockIdx.x * 4 + warp; p < NPAIR; p += wstride) {
        int pi = __ldg(ii + p);
        int po = __ldg(oi + p);

        const float4* xr = (const float4*)(feats + (size_t)pi * CIN);
        float x[CIN];
#pragma unroll
        for (int j = 0; j < 8; j++) ((float4*)x)[j] = __ldg(xr + j);

        float y0 = 0.f, y1 = 0.f, y2 = 0.f, y3 = 0.f;
#pragma unroll
        for (int i = 0; i < CIN; i += 2) {
            y0 = fmaf(x[i],     w0[i],     y0);
            y1 = fmaf(x[i],     w1[i],     y1);
            y2 = fmaf(x[i + 1], w0[i + 1], y2);
            y3 = fmaf(x[i + 1], w1[i + 1], y3);
        }
        float r0 = y0 + y2;   // channel 2*lane
        float r1 = y1 + y3;   // channel 2*lane+1

        // lane pair (2m, 2m+1) -> even lane issues one red.v4 for channels 4m..4m+3
        float s0 = __shfl_down_sync(0xffffffffu, r0, 1);
        float s1 = __shfl_down_sync(0xffffffffu, r1, 1);
        if ((lane & 1) == 0) {
            float* dst = out + (size_t)po * COUT + 2 * lane;  // = 4*(lane/2)
            asm volatile("red.global.add.v4.f32 [%0], {%1, %2, %3, %4};"
                         :: "l"(dst), "f"(r0), "f"(r1), "f"(s0), "f"(s1) : "memory");
        }
    }
}

// ---------------- L5: group stats ----------------
// blockDim = 256 (multiple of 16) so (flat_float4_index & 15) == (tid & 15):
// each thread touches exactly ONE group -> scalar accumulators, no spills.
__global__ __launch_bounds__(256) void reduce_kernel(const float* __restrict__ out) {
    __shared__ double ssum[16];
    int t = threadIdx.x;
    if (t < 16) ssum[t] = 0.0;
    __syncthreads();

    long long total4 = (long long)NPTS * COUT / 4;
    long long stride = (long long)gridDim.x * 256;
    float s = 0.f, q = 0.f;
    for (long long j = (long long)blockIdx.x * 256 + t; j < total4; j += stride) {
        float4 v = __ldg(((const float4*)out) + j);
        s += (v.x + v.y) + (v.z + v.w);
        q += (v.x * v.x + v.y * v.y) + (v.z * v.z + v.w * v.w);
    }
    s += __shfl_xor_sync(0xffffffffu, s, 16);
    q += __shfl_xor_sync(0xffffffffu, q, 16);
    s += __shfl_xor_sync(0xffffffffu, s, 1);
    q += __shfl_xor_sync(0xffffffffu, q, 1);
    int lane = t & 31;
    if ((lane & 16) == 0 && (lane & 1) == 0) {
        int g = lane >> 1;
        atomicAdd(&ssum[g],     (double)s);
        atomicAdd(&ssum[8 + g], (double)q);
    }
    __syncthreads();
    if (t < 16) atomicAdd(&g_stats[t], ssum[t]);
}

// ---------------- L6: normalize + affine + LeakyReLU ----------------
__global__ __launch_bounds__(256) void norm_kernel(
    float* __restrict__ out,
    const float* __restrict__ gamma,
    const float* __restrict__ beta)
{
    int t  = threadIdx.x;
    int c4 = t & 15;          // float4 slot within the 64-channel row
    int g  = c4 >> 1;

    double cnt = (double)NPTS * 8.0;
    double m   = g_stats[g] / cnt;
    double var = g_stats[8 + g] / cnt - m * m;
    float mean = (float)m;
    float rstd = (float)(1.0 / sqrt(var + EPS));

    float4 ga = __ldg(((const float4*)gamma) + c4);
    float4 be = __ldg(((const float4*)beta) + c4);
    float4 sc, of;
    sc.x = rstd * ga.x; of.x = be.x - mean * sc.x;
    sc.y = rstd * ga.y; of.y = be.y - mean * sc.y;
    sc.z = rstd * ga.z; of.z = be.z - mean * sc.z;
    sc.w = rstd * ga.w; of.w = be.w - mean * sc.w;

    long long total4 = (long long)NPTS * COUT / 4;
    long long stride = (long long)gridDim.x * 256;
    for (long long j = (long long)blockIdx.x * 256 + t; j < total4; j += stride) {
        float4 v = ((float4*)out)[j];
        v.x = fmaf(v.x, sc.x, of.x);
        v.y = fmaf(v.y, sc.y, of.y);
        v.z = fmaf(v.z, sc.z, of.z);
        v.w = fmaf(v.w, sc.w, of.w);
        v.x = v.x >= 0.f ? v.x : NEG_SLOPE * v.x;
        v.y = v.y >= 0.f ? v.y : NEG_SLOPE * v.y;
        v.z = v.z >= 0.f ? v.z : NEG_SLOPE * v.z;
        v.w = v.w >= 0.f ? v.w : NEG_SLOPE * v.w;
        ((float4*)out)[j] = v;
    }
}

// ---------------- launcher ----------------
extern "C" void kernel_launch(void* const* d_in, const int* in_sizes, int n_in,
                              void* d_out, int out_size) {
    const float* feats  = (const float*)d_in[0];
    const float* weight = (const float*)d_in[1];
    const float* gamma  = (const float*)d_in[2];
    const float* beta   = (const float*)d_in[3];
    const void*  in_idx = d_in[4];
    const void*  out_idx= d_in[5];
    float* out = (float*)d_out;

    cudaMemsetAsync(d_out, 0, (size_t)out_size * sizeof(float), 0);
    detect_kernel<<<1, 256>>>(in_idx);                                         // k1
    convert_kernel<<<660, 256>>>(in_idx, out_idx, 0, TOT_PAIRS / 2);           // k2
    convert_kernel<<<660, 256>>>(in_idx, out_idx, TOT_PAIRS / 2,
                                 TOT_PAIRS - TOT_PAIRS / 2);                   // k3
    conv_kernel<<<dim3(200, KOFF), 128>>>(feats, weight, out);                 // k4 <- ncu
    reduce_kernel<<<296, 256>>>(out);                                          // k5
    norm_kernel<<<592, 256>>>(out, gamma, beta);                               // k6
}

// round 8
// speedup vs baseline: 1.6848x; 1.4822x over previous
#include <cuda_runtime.h>
#include <cstdint>

#define NPTS   300000
#define KOFF   27
#define NPAIR  100000
#define CIN    32
#define COUT   64
#define TOT_PAIRS (KOFF * NPAIR)
#define EPS    1e-5
#define NEG_SLOPE 0.01f

// ---------------- device scratch (no allocations allowed) ----------------
__device__ int    g_is64;
__device__ int2   g_pair[TOT_PAIRS];   // (in_idx, out_idx) interleaved
__device__ double g_stats[16];         // [0..7]=sum per group, [8..15]=sumsq

// ---------------- L1: dtype detection + stats zero ----------------
// Reference declares int64 indices but JAX w/o x64 silently emits int32.
// Reading int32 data as int64 fuses two indices -> almost surely >= NPTS.
__global__ void detect_kernel(const void* in_idx) {
    int t = threadIdx.x;
    if (t == 0) g_is64 = 1;
    if (t < 16) g_stats[t] = 0.0;
    __syncthreads();
    const long long* p = (const long long*)in_idx;
    long long slots = TOT_PAIRS / 2;
    long long s = (slots * t) / 256;
    long long v = p[s];
    if (v < 0 || v >= NPTS) atomicAnd(&g_is64, 0);
}

// ---------------- L2+L3: convert indices into interleaved int2 ----------------
__global__ void convert_kernel(const void* in_idx, const void* out_idx, int base, int count) {
    int is64 = g_is64;
    int stride = gridDim.x * blockDim.x;
    for (int i = blockIdx.x * blockDim.x + threadIdx.x; i < count; i += stride) {
        int j = base + i;
        int a, b;
        if (is64) {
            a = (int)((const long long*)in_idx)[j];
            b = (int)((const long long*)out_idx)[j];
        } else {
            a = ((const int*)in_idx)[j];
            b = ((const int*)out_idx)[j];
        }
        g_pair[j] = make_int2(a, b);
    }
}

// ---------------- L4 (ncu capture slot): conv gather->matmul->scatter ----------------
// One warp handles TWO pairs per iteration (doubled MLP to cover the L2 gather
// latency chain; ptxas front-batches the 16 gather LDG.128). Lane owns channels
// (2*lane, 2*lane+1); weights in registers. Scatter: red.global.add.v2.f32
// from all 32 lanes (the proven R1 form).
__global__ __launch_bounds__(128) void conv_kernel(
    const float* __restrict__ feats,
    const float* __restrict__ weight,
    float* __restrict__ out)
{
    int k    = blockIdx.y;
    int lane = threadIdx.x & 31;
    int warp = threadIdx.x >> 5;

    const float* W = weight + k * (CIN * COUT);
    float w0[CIN], w1[CIN];
#pragma unroll
    for (int i = 0; i < CIN; i++) {
        float2 wv = *(const float2*)(W + i * COUT + 2 * lane);
        w0[i] = wv.x; w1[i] = wv.y;
    }

    const int2* pp = g_pair + k * NPAIR;
    int wstride = gridDim.x * 4;

    for (int p = blockIdx.x * 4 + warp; p < NPAIR; p += 2 * wstride) {
        int pB = p + wstride;
        bool hasB = (pB < NPAIR);

        int2 ioA = __ldcs(pp + p);
        int2 ioB = hasB ? __ldcs(pp + pB) : ioA;

        const float4* xA = (const float4*)(feats + (size_t)ioA.x * CIN);
        const float4* xB = (const float4*)(feats + (size_t)ioB.x * CIN);

        float a0 = 0.f, a1 = 0.f, b0 = 0.f, b1 = 0.f;
        float a2 = 0.f, a3 = 0.f, b2 = 0.f, b3 = 0.f;
#pragma unroll
        for (int j = 0; j < 8; j++) {
            float4 va = __ldg(xA + j);
            float4 vb = __ldg(xB + j);
            a0 = fmaf(va.x, w0[4 * j],     a0);
            a1 = fmaf(va.x, w1[4 * j],     a1);
            a2 = fmaf(va.y, w0[4 * j + 1], a2);
            a3 = fmaf(va.y, w1[4 * j + 1], a3);
            a0 = fmaf(va.z, w0[4 * j + 2], a0);
            a1 = fmaf(va.z, w1[4 * j + 2], a1);
            a2 = fmaf(va.w, w0[4 * j + 3], a2);
            a3 = fmaf(va.w, w1[4 * j + 3], a3);
            b0 = fmaf(vb.x, w0[4 * j],     b0);
            b1 = fmaf(vb.x, w1[4 * j],     b1);
            b2 = fmaf(vb.y, w0[4 * j + 1], b2);
            b3 = fmaf(vb.y, w1[4 * j + 1], b3);
            b0 = fmaf(vb.z, w0[4 * j + 2], b0);
            b1 = fmaf(vb.z, w1[4 * j + 2], b1);
            b2 = fmaf(vb.w, w0[4 * j + 3], b2);
            b3 = fmaf(vb.w, w1[4 * j + 3], b3);
        }
        float rA0 = a0 + a2, rA1 = a1 + a3;
        float rB0 = b0 + b2, rB1 = b1 + b3;

        float* dstA = out + (size_t)ioA.y * COUT + 2 * lane;
        asm volatile("red.global.add.v2.f32 [%0], {%1, %2};"
                     :: "l"(dstA), "f"(rA0), "f"(rA1) : "memory");
        if (hasB) {
            float* dstB = out + (size_t)ioB.y * COUT + 2 * lane;
            asm volatile("red.global.add.v2.f32 [%0], {%1, %2};"
                         :: "l"(dstB), "f"(rB0), "f"(rB1) : "memory");
        }
    }
}

// ---------------- L5: group stats ----------------
// blockDim = 256 (multiple of 16) so (flat_float4_index & 15) == (tid & 15):
// each thread touches exactly ONE group -> scalar accumulators, no spills.
__global__ __launch_bounds__(256) void reduce_kernel(const float* __restrict__ out) {
    __shared__ double ssum[16];
    int t = threadIdx.x;
    if (t < 16) ssum[t] = 0.0;
    __syncthreads();

    long long total4 = (long long)NPTS * COUT / 4;
    long long stride = (long long)gridDim.x * 256;
    float s = 0.f, q = 0.f;
    for (long long j = (long long)blockIdx.x * 256 + t; j < total4; j += stride) {
        float4 v = __ldg(((const float4*)out) + j);
        s += (v.x + v.y) + (v.z + v.w);
        q += (v.x * v.x + v.y * v.y) + (v.z * v.z + v.w * v.w);
    }
    s += __shfl_xor_sync(0xffffffffu, s, 16);
    q += __shfl_xor_sync(0xffffffffu, q, 16);
    s += __shfl_xor_sync(0xffffffffu, s, 1);
    q += __shfl_xor_sync(0xffffffffu, q, 1);
    int lane = t & 31;
    if ((lane & 16) == 0 && (lane & 1) == 0) {
        int g = lane >> 1;
        atomicAdd(&ssum[g],     (double)s);
        atomicAdd(&ssum[8 + g], (double)q);
    }
    __syncthreads();
    if (t < 16) atomicAdd(&g_stats[t], ssum[t]);
}

// ---------------- L6: normalize + affine + LeakyReLU ----------------
__global__ __launch_bounds__(256) void norm_kernel(
    float* __restrict__ out,
    const float* __restrict__ gamma,
    const float* __restrict__ beta)
{
    int t  = threadIdx.x;
    int c4 = t & 15;          // float4 slot within the 64-channel row
    int g  = c4 >> 1;

    double cnt = (double)NPTS * 8.0;
    double m   = g_stats[g] / cnt;
    double var = g_stats[8 + g] / cnt - m * m;
    float mean = (float)m;
    float rstd = (float)(1.0 / sqrt(var + EPS));

    float4 ga = __ldg(((const float4*)gamma) + c4);
    float4 be = __ldg(((const float4*)beta) + c4);
    float4 sc, of;
    sc.x = rstd * ga.x; of.x = be.x - mean * sc.x;
    sc.y = rstd * ga.y; of.y = be.y - mean * sc.y;
    sc.z = rstd * ga.z; of.z = be.z - mean * sc.z;
    sc.w = rstd * ga.w; of.w = be.w - mean * sc.w;

    long long total4 = (long long)NPTS * COUT / 4;
    long long stride = (long long)gridDim.x * 256;
    for (long long j = (long long)blockIdx.x * 256 + t; j < total4; j += stride) {
        float4 v = ((float4*)out)[j];
        v.x = fmaf(v.x, sc.x, of.x);
        v.y = fmaf(v.y, sc.y, of.y);
        v.z = fmaf(v.z, sc.z, of.z);
        v.w = fmaf(v.w, sc.w, of.w);
        v.x = v.x >= 0.f ? v.x : NEG_SLOPE * v.x;
        v.y = v.y >= 0.f ? v.y : NEG_SLOPE * v.y;
        v.z = v.z >= 0.f ? v.z : NEG_SLOPE * v.z;
        v.w = v.w >= 0.f ? v.w : NEG_SLOPE * v.w;
        ((float4*)out)[j] = v;
    }
}

// ---------------- launcher ----------------
extern "C" void kernel_launch(void* const* d_in, const int* in_sizes, int n_in,
                              void* d_out, int out_size) {
    const float* feats  = (const float*)d_in[0];
    const float* weight = (const float*)d_in[1];
    const float* gamma  = (const float*)d_in[2];
    const float* beta   = (const float*)d_in[3];
    const void*  in_idx = d_in[4];
    const void*  out_idx= d_in[5];
    float* out = (float*)d_out;

    cudaMemsetAsync(d_out, 0, (size_t)out_size * sizeof(float), 0);
    detect_kernel<<<1, 256>>>(in_idx);                                         // k1
    convert_kernel<<<660, 256>>>(in_idx, out_idx, 0, TOT_PAIRS / 2);           // k2
    convert_kernel<<<660, 256>>>(in_idx, out_idx, TOT_PAIRS / 2,
                                 TOT_PAIRS - TOT_PAIRS / 2);                   // k3
    conv_kernel<<<dim3(100, KOFF), 128>>>(feats, weight, out);                 // k4 <- ncu
    reduce_kernel<<<296, 256>>>(out);                                          // k5
    norm_kernel<<<592, 256>>>(out, gamma, beta);                               // k6
}

// round 10
// speedup vs baseline: 1.8184x; 1.0793x over previous
#include <cuda_runtime.h>
#include <cstdint>

#define NPTS   300000
#define KOFF   27
#define NPAIR  100000
#define CIN    32
#define COUT   64
#define TOT_PAIRS (KOFF * NPAIR)
#define EPS    1e-5
#define NEG_SLOPE 0.01f
#define NBUCK  8
#define BUCK_DIV 37500          // in/37500 <= 7 for in < 300000
#define NSEG   (KOFF * NBUCK)   // 216
#define HIST_BLOCKS 660

// ---------------- device scratch (no allocations allowed) ----------------
// g_histPart is fully overwritten every replay (plain stores) -> no pre-zero.
__device__ int    g_histPart[HIST_BLOCKS][NSEG];   // per-block partial histograms
__device__ int    g_segStart[NSEG + 1];
__device__ int    g_cursor[NSEG];
__device__ int2   g_sorted[TOT_PAIRS];   // (in,out) pairs, bucket-sorted per k
__device__ double g_stats[16];           // zeroed by scan_kernel each replay

// ---------------- pure, deterministic idx-dtype detection ----------------
// Reference declares int64 indices but JAX w/o x64 silently emits int32.
// Reading int32 data as int64 fuses two indices (lo + hi*2^32); hi is a
// ~uniform idx so virtually every sample blows past NPTS unless truly int64.
__device__ __forceinline__ int detect64(const void* in_idx) {
    const long long* p = (const long long*)in_idx;
    int ok = 1;
#pragma unroll
    for (int s = 0; s < 16; s++) {
        long long slot = (long long)s * (TOT_PAIRS / 2 - 1) / 15;
        long long v = __ldg(p + slot);
        if (v < 0 || v >= NPTS) ok = 0;
    }
    return ok;
}

// ---------------- k1: per-block histogram over (k, bucket) ----------------
__global__ __launch_bounds__(256) void hist_kernel(const void* in_idx) {
    __shared__ int h[NSEG];
    __shared__ int s64;
    int t = threadIdx.x;
    for (int i = t; i < NSEG; i += blockDim.x) h[i] = 0;
    if (t == 0) s64 = detect64(in_idx);
    __syncthreads();
    int is64 = s64;
    int stride = gridDim.x * blockDim.x;
    for (int j = blockIdx.x * blockDim.x + t; j < TOT_PAIRS; j += stride) {
        int in = is64 ? (int)((const long long*)in_idx)[j]
                      : ((const int*)in_idx)[j];
        int k = j / NPAIR;
        int b = in / BUCK_DIV;
        atomicAdd(&h[k * NBUCK + b], 1);
    }
    __syncthreads();
    for (int i = t; i < NSEG; i += blockDim.x)
        g_histPart[blockIdx.x][i] = h[i];           // plain store, no pre-zero needed
}

// ---------------- k2: sum partials + exclusive scan + zero stats ----------
__global__ __launch_bounds__(256) void scan_kernel() {
    __shared__ int sm[256];
    int t = threadIdx.x;
    int tot = 0;
    if (t < NSEG) {
        for (int b = 0; b < HIST_BLOCKS; b++) tot += g_histPart[b][t];
    }
    sm[t] = tot;
    __syncthreads();
    for (int d = 1; d < 256; d <<= 1) {
        int v = (t >= d) ? sm[t - d] : 0;
        __syncthreads();
        sm[t] += v;
        __syncthreads();
    }
    int excl = (t == 0) ? 0 : sm[t - 1];
    if (t <= NSEG) g_segStart[t] = excl;
    if (t < NSEG)  g_cursor[t]   = excl;
    if (t < 16)    g_stats[t]    = 0.0;   // re-zeroed every replay, before reduce
}

// ---------------- k3: scatter pairs into bucket-sorted order ----------------
__global__ __launch_bounds__(256) void fill_kernel(const void* in_idx, const void* out_idx) {
    __shared__ int s64;
    if (threadIdx.x == 0) s64 = detect64(in_idx);
    __syncthreads();
    int is64 = s64;
    int stride = gridDim.x * blockDim.x;
    for (int j = blockIdx.x * blockDim.x + threadIdx.x; j < TOT_PAIRS; j += stride) {
        int in, out;
        if (is64) {
            in  = (int)((const long long*)in_idx)[j];
            out = (int)((const long long*)out_idx)[j];
        } else {
            in  = ((const int*)in_idx)[j];
            out = ((const int*)out_idx)[j];
        }
        int k = j / NPAIR;
        int b = in / BUCK_DIV;
        int pos = atomicAdd(&g_cursor[k * NBUCK + b], 1);
        g_sorted[pos] = make_int2(in, out);
    }
}

// ---------------- k4 (ncu capture slot): conv over bucket-ordered pairs ----
// R1-proven body: one warp per pair, lane owns channels (2*lane, 2*lane+1),
// weights of offset k in registers, feats row warp-broadcast 8x LDG.128,
// scatter via red.global.add.v2.f32 from all 32 lanes. Pairs are bucket-
// sorted by in_idx and all blocks sweep buckets in the same order, so
// concurrent gathers hit a hot ~4.8MB L2 slice instead of missing to DRAM.
__global__ __launch_bounds__(128) void conv_kernel(
    const float* __restrict__ feats,
    const float* __restrict__ weight,
    float* __restrict__ out)
{
    int k    = blockIdx.y;
    int lane = threadIdx.x & 31;
    int warp = threadIdx.x >> 5;

    const float* W = weight + k * (CIN * COUT);
    float w0[CIN], w1[CIN];
#pragma unroll
    for (int i = 0; i < CIN; i++) {
        float2 wv = *(const float2*)(W + i * COUT + 2 * lane);
        w0[i] = wv.x; w1[i] = wv.y;
    }

    int wstride = gridDim.x * 4;

    for (int b = 0; b < NBUCK; b++) {
        int s0 = __ldg(&g_segStart[k * NBUCK + b]);
        int s1 = __ldg(&g_segStart[k * NBUCK + b + 1]);

        for (int p = s0 + blockIdx.x * 4 + warp; p < s1; p += wstride) {
            int2 io = __ldcs(&g_sorted[p]);

            const float4* xr = (const float4*)(feats + (size_t)io.x * CIN);
            float x[CIN];
#pragma unroll
            for (int j = 0; j < 8; j++) ((float4*)x)[j] = __ldg(xr + j);

            float y0 = 0.f, y1 = 0.f, y2 = 0.f, y3 = 0.f;
#pragma unroll
            for (int i = 0; i < CIN; i += 2) {
                y0 = fmaf(x[i],     w0[i],     y0);
                y1 = fmaf(x[i],     w1[i],     y1);
                y2 = fmaf(x[i + 1], w0[i + 1], y2);
                y3 = fmaf(x[i + 1], w1[i + 1], y3);
            }
            float r0 = y0 + y2;
            float r1 = y1 + y3;

            float* dst = out + (size_t)io.y * COUT + 2 * lane;
            asm volatile("red.global.add.v2.f32 [%0], {%1, %2};"
                         :: "l"(dst), "f"(r0), "f"(r1) : "memory");
        }
    }
}

// ---------------- k5: group stats ----------------
// blockDim = 256 (multiple of 16) so (flat_float4_index & 15) == (tid & 15):
// each thread touches exactly ONE group -> scalar accumulators, no spills.
__global__ __launch_bounds__(256) void reduce_kernel(const float* __restrict__ out) {
    __shared__ double ssum[16];
    int t = threadIdx.x;
    if (t < 16) ssum[t] = 0.0;
    __syncthreads();

    long long total4 = (long long)NPTS * COUT / 4;
    long long stride = (long long)gridDim.x * 256;
    float s = 0.f, q = 0.f;
    for (long long j = (long long)blockIdx.x * 256 + t; j < total4; j += stride) {
        float4 v = __ldg(((const float4*)out) + j);
        s += (v.x + v.y) + (v.z + v.w);
        q += (v.x * v.x + v.y * v.y) + (v.z * v.z + v.w * v.w);
    }
    s += __shfl_xor_sync(0xffffffffu, s, 16);
    q += __shfl_xor_sync(0xffffffffu, q, 16);
    s += __shfl_xor_sync(0xffffffffu, s, 1);
    q += __shfl_xor_sync(0xffffffffu, q, 1);
    int lane = t & 31;
    if ((lane & 16) == 0 && (lane & 1) == 0) {
        int g = lane >> 1;
        atomicAdd(&ssum[g],     (double)s);
        atomicAdd(&ssum[8 + g], (double)q);
    }
    __syncthreads();
    if (t < 16) atomicAdd(&g_stats[t], ssum[t]);
}

// ---------------- k6: normalize + affine + LeakyReLU ----------------
__global__ __launch_bounds__(256) void norm_kernel(
    float* __restrict__ out,
    const float* __restrict__ gamma,
    const float* __restrict__ beta)
{
    int t  = threadIdx.x;
    int c4 = t & 15;          // float4 slot within the 64-channel row
    int g  = c4 >> 1;

    double cnt = (double)NPTS * 8.0;
    double m   = g_stats[g] / cnt;
    double var = g_stats[8 + g] / cnt - m * m;
    float mean = (float)m;
    float rstd = (float)(1.0 / sqrt(var + EPS));

    float4 ga = __ldg(((const float4*)gamma) + c4);
    float4 be = __ldg(((const float4*)beta) + c4);
    float4 sc, of;
    sc.x = rstd * ga.x; of.x = be.x - mean * sc.x;
    sc.y = rstd * ga.y; of.y = be.y - mean * sc.y;
    sc.z = rstd * ga.z; of.z = be.z - mean * sc.z;
    sc.w = rstd * ga.w; of.w = be.w - mean * sc.w;

    long long total4 = (long long)NPTS * COUT / 4;
    long long stride = (long long)gridDim.x * 256;
    for (long long j = (long long)blockIdx.x * 256 + t; j < total4; j += stride) {
        float4 v = ((float4*)out)[j];
        v.x = fmaf(v.x, sc.x, of.x);
        v.y = fmaf(v.y, sc.y, of.y);
        v.z = fmaf(v.z, sc.z, of.z);
        v.w = fmaf(v.w, sc.w, of.w);
        v.x = v.x >= 0.f ? v.x : NEG_SLOPE * v.x;
        v.y = v.y >= 0.f ? v.y : NEG_SLOPE * v.y;
        v.z = v.z >= 0.f ? v.z : NEG_SLOPE * v.z;
        v.w = v.w >= 0.f ? v.w : NEG_SLOPE * v.w;
        ((float4*)out)[j] = v;
    }
}

// ---------------- launcher ----------------
extern "C" void kernel_launch(void* const* d_in, const int* in_sizes, int n_in,
                              void* d_out, int out_size) {
    const float* feats  = (const float*)d_in[0];
    const float* weight = (const float*)d_in[1];
    const float* gamma  = (const float*)d_in[2];
    const float* beta   = (const float*)d_in[3];
    const void*  in_idx = d_in[4];
    const void*  out_idx= d_in[5];
    float* out = (float*)d_out;

    cudaMemsetAsync(d_out, 0, (size_t)out_size * sizeof(float), 0);

    hist_kernel<<<HIST_BLOCKS, 256>>>(in_idx);                 // kernel 1
    scan_kernel<<<1, 256>>>();                                 // kernel 2
    fill_kernel<<<660, 256>>>(in_idx, out_idx);                // kernel 3
    conv_kernel<<<dim3(27, KOFF), 128>>>(feats, weight, out);  // kernel 4 <- ncu
    reduce_kernel<<<296, 256>>>(out);                          // kernel 5
    norm_kernel<<<592, 256>>>(out, gamma, beta);               // kernel 6
}